// round 1
// baseline (speedup 1.0000x reference)
#include <cuda_runtime.h>
#include <math.h>

// Problem constants (fixed by the dataset)
#define D            128
#define E_ATT_MAX    300000
#define E_REP_MAX    600000
#define TAU_INV      20.0f                  // 1/0.05
#define INV_2SIG2    (1.0f / 1.125f)        // 1/(2*0.75^2)

#define SUM_BLOCKS   512
#define SUM_THREADS  256

// Scratch (no allocation allowed -> device globals)
__device__ float g_sim1[E_ATT_MAX];   // sim/tau for attractive edges
__device__ float g_sim2[E_REP_MAX];   // sim/tau for repulsive edges
__device__ int   g_max1;              // float bits (sims >= 0 so int-compare is monotone)
__device__ int   g_max2;
__device__ float g_partials[SUM_BLOCKS];
__device__ float g_S2;

__global__ void init_kernel() {
    g_max1 = 0;   // 0.0f bits; all sims/tau > 0
    g_max2 = 0;
}

// One warp per edge: 32 lanes x float4 = 128 floats per endpoint row.
__global__ void edge_sim_kernel(const float* __restrict__ x,
                                const int*   __restrict__ edges, int E,
                                float* __restrict__ sim_out,
                                int*   __restrict__ gmax) {
    __shared__ int smax;
    if (threadIdx.x == 0) smax = 0;
    __syncthreads();

    const int warp_id = (blockIdx.x * blockDim.x + threadIdx.x) >> 5;
    const int lane    = threadIdx.x & 31;

    float s = 0.0f;
    if (warp_id < E) {
        const int i = __ldg(&edges[warp_id]);
        const int j = __ldg(&edges[E + warp_id]);
        const float4* __restrict__ xi = (const float4*)(x + (size_t)i * D);
        const float4* __restrict__ xj = (const float4*)(x + (size_t)j * D);
        float4 a = __ldg(&xi[lane]);
        float4 b = __ldg(&xj[lane]);
        float dx = a.x - b.x, dy = a.y - b.y, dz = a.z - b.z, dw = a.w - b.w;
        float acc = dx*dx + dy*dy + dz*dz + dw*dw;
        #pragma unroll
        for (int off = 16; off; off >>= 1)
            acc += __shfl_xor_sync(0xffffffffu, acc, off);
        float l2 = sqrtf(acc);
        s = expf(-l2 * INV_2SIG2) * TAU_INV;   // sim/tau
        if (lane == 0) sim_out[warp_id] = s;
    }
    // exact max: order-independent -> deterministic
    if (lane == 0 && s > 0.0f) atomicMax(&smax, __float_as_int(s));
    __syncthreads();
    if (threadIdx.x == 0) atomicMax(gmax, smax);
}

// Deterministic stage-1 sum of exp(sim2 - m2): fixed grid, fixed per-thread order.
__global__ void sum_exp_kernel(const float* __restrict__ sim2, int E) {
    __shared__ float sdata[SUM_THREADS];
    const float m2 = __int_as_float(g_max2);
    float acc = 0.0f;
    for (int i = blockIdx.x * blockDim.x + threadIdx.x; i < E;
         i += gridDim.x * blockDim.x)
        acc += expf(sim2[i] - m2);
    sdata[threadIdx.x] = acc;
    __syncthreads();
    #pragma unroll
    for (int sft = SUM_THREADS / 2; sft > 0; sft >>= 1) {
        if (threadIdx.x < sft) sdata[threadIdx.x] += sdata[threadIdx.x + sft];
        __syncthreads();
    }
    if (threadIdx.x == 0) g_partials[blockIdx.x] = sdata[0];
}

// Deterministic stage-2: single block reduces the fixed partial array.
__global__ void reduce_partials_kernel() {
    __shared__ float sdata[SUM_THREADS];
    float acc = 0.0f;
    for (int i = threadIdx.x; i < SUM_BLOCKS; i += SUM_THREADS)
        acc += g_partials[i];
    sdata[threadIdx.x] = acc;
    __syncthreads();
    #pragma unroll
    for (int sft = SUM_THREADS / 2; sft > 0; sft >>= 1) {
        if (threadIdx.x < sft) sdata[threadIdx.x] += sdata[threadIdx.x + sft];
        __syncthreads();
    }
    if (threadIdx.x == 0) g_S2 = sdata[0];
}

__global__ void final_kernel(const float* __restrict__ sim1, int E,
                             float* __restrict__ out) {
    const int e = blockIdx.x * blockDim.x + threadIdx.x;
    if (e >= E) return;
    const float m1 = __int_as_float(g_max1);
    const float S2 = g_S2;
    const float num = expf(sim1[e] - m1);
    out[e] = -logf(num / (num + S2));
}

extern "C" void kernel_launch(void* const* d_in, const int* in_sizes, int n_in,
                              void* d_out, int out_size) {
    const float* x         = (const float*)d_in[0];
    const int*   att_edges = (const int*)d_in[1];
    const int*   rep_edges = (const int*)d_in[2];
    float*       out       = (float*)d_out;

    const int E_att = in_sizes[1] / 2;   // [2, E_att] row-major
    const int E_rep = in_sizes[2] / 2;

    float* sim1; cudaGetSymbolAddress((void**)&sim1, g_sim1);
    float* sim2; cudaGetSymbolAddress((void**)&sim2, g_sim2);
    int*   max1; cudaGetSymbolAddress((void**)&max1, g_max1);
    int*   max2; cudaGetSymbolAddress((void**)&max2, g_max2);

    init_kernel<<<1, 1>>>();

    const int threads = 256;
    const int warps_per_block = threads / 32;

    {
        int blocks = (E_rep + warps_per_block - 1) / warps_per_block;
        edge_sim_kernel<<<blocks, threads>>>(x, rep_edges, E_rep, sim2, max2);
    }
    {
        int blocks = (E_att + warps_per_block - 1) / warps_per_block;
        edge_sim_kernel<<<blocks, threads>>>(x, att_edges, E_att, sim1, max1);
    }

    sum_exp_kernel<<<SUM_BLOCKS, SUM_THREADS>>>(sim2, E_rep);
    reduce_partials_kernel<<<1, SUM_THREADS>>>();

    final_kernel<<<(E_att + threads - 1) / threads, threads>>>(sim1, E_att, out);
}

// round 2
// speedup vs baseline: 1.2441x; 1.2441x over previous
#include <cuda_runtime.h>
#include <math.h>

// Problem constants (fixed by the dataset)
#define D            128
#define E_ATT_MAX    300000
#define E_REP_MAX    600000
#define TAU_INV      20.0f                  // 1/0.05
#define INV_2SIG2    (1.0f / 1.125f)        // 1/(2*0.75^2)

#define EDGES_PER_BLOCK 16                  // 8 warps x 2 edges
#define REP_BLOCKS_MAX  ((E_REP_MAX + EDGES_PER_BLOCK - 1) / EDGES_PER_BLOCK)
#define CMB_THREADS     256
#define NEG_INF         (-__int_as_float(0x7f800000))

// Scratch (no allocation allowed -> device globals)
__device__ float g_sim1[E_ATT_MAX];          // sim/tau for attractive edges
__device__ float g_block_m[REP_BLOCKS_MAX];  // per-block max  (rep)
__device__ float g_block_s[REP_BLOCKS_MAX];  // per-block sum  (rep, shifted by block max)
__device__ int   g_max1;                     // float bits; sims/tau > 0 so int cmp is monotone
__device__ float g_S2;
__device__ float g_m2;

__global__ void init_kernel() { g_max1 = 0; }

// Fused gather: blocks [0, nblocks_rep) handle repulsive edges with flash-style
// per-block (max, sum); blocks [nblocks_rep, ...) handle attractive edges
// (store sim/tau + global int-max). One warp processes TWO edges (MLP=4).
__global__ void fused_edge_kernel(const float* __restrict__ x,
                                  const int*   __restrict__ att, int E_att,
                                  const int*   __restrict__ rep, int E_rep,
                                  int nblocks_rep,
                                  float* __restrict__ sim1,
                                  int*   __restrict__ gmax1,
                                  float* __restrict__ block_m,
                                  float* __restrict__ block_s) {
    __shared__ float ssim[EDGES_PER_BLOCK];
    __shared__ int   smax;

    const int warp = threadIdx.x >> 5;      // 0..7
    const int lane = threadIdx.x & 31;
    const bool is_rep = (blockIdx.x < nblocks_rep);

    const int* __restrict__ edges = is_rep ? rep : att;
    const int  E   = is_rep ? E_rep : E_att;
    const int  blk = is_rep ? blockIdx.x : (blockIdx.x - nblocks_rep);
    const int  e0  = blk * EDGES_PER_BLOCK + warp * 2;
    const int  e1  = e0 + 1;
    const bool v0  = (e0 < E);
    const bool v1  = (e1 < E);
    const int  e0c = v0 ? e0 : (E - 1);     // clamp: loads always safe, no divergence
    const int  e1c = v1 ? e1 : (E - 1);

    if (!is_rep && threadIdx.x == 0) smax = 0;

    // Gather indices (broadcast loads), then batch 4 independent float4 chains.
    const int i0 = __ldg(&edges[e0c]);
    const int j0 = __ldg(&edges[E + e0c]);
    const int i1 = __ldg(&edges[e1c]);
    const int j1 = __ldg(&edges[E + e1c]);

    const float4* __restrict__ p_i0 = (const float4*)(x + (size_t)i0 * D);
    const float4* __restrict__ p_j0 = (const float4*)(x + (size_t)j0 * D);
    const float4* __restrict__ p_i1 = (const float4*)(x + (size_t)i1 * D);
    const float4* __restrict__ p_j1 = (const float4*)(x + (size_t)j1 * D);

    float4 a0 = __ldg(&p_i0[lane]);
    float4 b0 = __ldg(&p_j0[lane]);
    float4 a1 = __ldg(&p_i1[lane]);
    float4 b1 = __ldg(&p_j1[lane]);

    float dx, dy, dz, dw;
    dx = a0.x - b0.x; dy = a0.y - b0.y; dz = a0.z - b0.z; dw = a0.w - b0.w;
    float acc0 = dx*dx + dy*dy + dz*dz + dw*dw;
    dx = a1.x - b1.x; dy = a1.y - b1.y; dz = a1.z - b1.z; dw = a1.w - b1.w;
    float acc1 = dx*dx + dy*dy + dz*dz + dw*dw;

    #pragma unroll
    for (int off = 16; off; off >>= 1) {
        acc0 += __shfl_xor_sync(0xffffffffu, acc0, off);
        acc1 += __shfl_xor_sync(0xffffffffu, acc1, off);
    }
    const float s0 = expf(-sqrtf(acc0) * INV_2SIG2) * TAU_INV;   // sim/tau
    const float s1 = expf(-sqrtf(acc1) * INV_2SIG2) * TAU_INV;

    if (is_rep) {
        if (lane == 0) {
            ssim[warp * 2 + 0] = v0 ? s0 : NEG_INF;
            ssim[warp * 2 + 1] = v1 ? s1 : NEG_INF;
        }
        __syncthreads();
        // First 16 lanes of warp 0: deterministic max + shifted-exp sum.
        if (warp == 0) {
            float v = (lane < EDGES_PER_BLOCK) ? ssim[lane] : NEG_INF;
            float m = v;
            #pragma unroll
            for (int off = 8; off; off >>= 1)
                m = fmaxf(m, __shfl_xor_sync(0xffffffffu, m, off));
            float e = (lane < EDGES_PER_BLOCK) ? expf(v - m) : 0.0f; // exp(-inf-m)=0
            #pragma unroll
            for (int off = 8; off; off >>= 1)
                e += __shfl_xor_sync(0xffffffffu, e, off);
            if (lane == 0) { block_m[blk] = m; block_s[blk] = e; }
        }
    } else {
        if (lane == 0) {
            if (v0) sim1[e0] = s0;
            if (v1) sim1[e1] = s1;
            int mbits = __float_as_int(v0 ? (v1 ? fmaxf(s0, s1) : s0) : s1);
            atomicMax(&smax, mbits);
        }
        __syncthreads();
        if (threadIdx.x == 0) atomicMax(gmax1, smax);
    }
}

// Single-block deterministic combine: m2 = max(block_m), S2 = sum(block_s * e^{m_b - m2})
__global__ void combine_kernel(int nblocks_rep) {
    __shared__ float sdata[CMB_THREADS];
    // Phase 1: max
    float m = NEG_INF;
    for (int i = threadIdx.x; i < nblocks_rep; i += CMB_THREADS)
        m = fmaxf(m, g_block_m[i]);
    sdata[threadIdx.x] = m;
    __syncthreads();
    #pragma unroll
    for (int sft = CMB_THREADS / 2; sft > 0; sft >>= 1) {
        if (threadIdx.x < sft)
            sdata[threadIdx.x] = fmaxf(sdata[threadIdx.x], sdata[threadIdx.x + sft]);
        __syncthreads();
    }
    const float m2 = sdata[0];
    __syncthreads();
    // Phase 2: shifted sum
    float acc = 0.0f;
    for (int i = threadIdx.x; i < nblocks_rep; i += CMB_THREADS)
        acc += g_block_s[i] * expf(g_block_m[i] - m2);
    sdata[threadIdx.x] = acc;
    __syncthreads();
    #pragma unroll
    for (int sft = CMB_THREADS / 2; sft > 0; sft >>= 1) {
        if (threadIdx.x < sft) sdata[threadIdx.x] += sdata[threadIdx.x + sft];
        __syncthreads();
    }
    if (threadIdx.x == 0) { g_S2 = sdata[0]; g_m2 = m2; }
}

__global__ void final_kernel(const float* __restrict__ sim1, int E,
                             float* __restrict__ out) {
    const int e = blockIdx.x * blockDim.x + threadIdx.x;
    if (e >= E) return;
    const float m1  = __int_as_float(g_max1);
    const float S2  = g_S2;
    const float num = expf(sim1[e] - m1);
    out[e] = -logf(num / (num + S2));
}

extern "C" void kernel_launch(void* const* d_in, const int* in_sizes, int n_in,
                              void* d_out, int out_size) {
    const float* x         = (const float*)d_in[0];
    const int*   att_edges = (const int*)d_in[1];
    const int*   rep_edges = (const int*)d_in[2];
    float*       out       = (float*)d_out;

    const int E_att = in_sizes[1] / 2;   // [2, E] row-major
    const int E_rep = in_sizes[2] / 2;

    float* sim1;    cudaGetSymbolAddress((void**)&sim1,    g_sim1);
    int*   max1;    cudaGetSymbolAddress((void**)&max1,    g_max1);
    float* block_m; cudaGetSymbolAddress((void**)&block_m, g_block_m);
    float* block_s; cudaGetSymbolAddress((void**)&block_s, g_block_s);

    const int nblocks_rep = (E_rep + EDGES_PER_BLOCK - 1) / EDGES_PER_BLOCK;
    const int nblocks_att = (E_att + EDGES_PER_BLOCK - 1) / EDGES_PER_BLOCK;

    init_kernel<<<1, 1>>>();

    fused_edge_kernel<<<nblocks_rep + nblocks_att, 256>>>(
        x, att_edges, E_att, rep_edges, E_rep, nblocks_rep,
        sim1, max1, block_m, block_s);

    combine_kernel<<<1, CMB_THREADS>>>(nblocks_rep);

    final_kernel<<<(E_att + 255) / 256, 256>>>(sim1, E_att, out);
}